// round 4
// baseline (speedup 1.0000x reference)
#include <cuda_runtime.h>
#include <cuda_bf16.h>

// Problem constants
#define NN 16
#define CC 64
#define HH 112
#define WW 112
#define HWHW (HH*WW)               // 12544
#define TENSOR_ELEMS (NN*CC*HWHW)  // 12,845,056
#define PKW (NN*16*HWHW)           // packed words (4 channels / u32)

#define TH 16
#define TW 16

#define R_S  (10.0f/255.0f)
#define HT_S (10.0f/127.0f)

// -------- scratch (device globals; no allocation allowed) ----------
__device__ unsigned g_act1[PKW];          // u8 codes, [n][c4][h][w]
__device__ unsigned g_act2[PKW];
__device__ unsigned g_act3[PKW];
__device__ unsigned g_idq [PKW];          // s8 codes of qhtanh(identity0)
__device__ unsigned g_sgn [3*16*9*64];    // stages 1..3: packed ±1 s8, [i-1][ci4][tap][co]
__device__ float    g_w0  [64*9*64];      // stage0 ±1 floats, [ci][tap][co]
__device__ float    g_dsq [CC*CC];        // int8-quant 1x1 weights, [ci][co]
__device__ float    g_wsc [4*CC];         // binary weight per-channel scales
__device__ float    g_A   [4*CC];         // fused conv-scale * bn-inv (stage>0 includes R)
__device__ float    g_B   [4*CC];         // bn bias
__device__ float    g_bninv4 [CC];
__device__ float    g_bnbias4[CC];

// -------- quantizer helpers (round-half-even matches jnp) -----------
__device__ __forceinline__ float qhtanh_f(float x) {
    float c = fminf(fmaxf(x, -10.0f), 10.0f);
    float r = rintf(__fdiv_rn(c, HT_S));
    r = fminf(fmaxf(r, -127.0f), 127.0f);
    return r * HT_S;
}
__device__ __forceinline__ float qrelu_f(float x) {
    float c = fminf(fmaxf(x, 0.0f), 10.0f);
    float r = rintf(__fdiv_rn(c, R_S));
    r = fminf(fmaxf(r, 0.0f), 255.0f);
    return r * R_S;
}
__device__ __forceinline__ unsigned qrelu_code(float x) {
    float c = fminf(fmaxf(x, 0.0f), 10.0f);
    float r = rintf(__fdiv_rn(c, R_S));
    return (unsigned)(int)fminf(r, 255.0f);
}
__device__ __forceinline__ int dp4a_us(unsigned a, unsigned b, int c) {
    int r;
    asm("dp4a.u32.s32 %0, %1, %2, %3;" : "=r"(r) : "r"(a), "r"(b), "r"(c));
    return r;
}

// -------- per-channel AVE scale for binary weights -------------------
__global__ void scale_kernel(const float* __restrict__ w, float* __restrict__ wsc) {
    int b  = blockIdx.x;          // 0..255
    const float* wc = w + b*576;
    __shared__ float red[256];
    float s = 0.f;
    for (int e = threadIdx.x; e < 576; e += 256) s += fabsf(wc[e]);
    red[threadIdx.x] = s;
    __syncthreads();
    for (int off = 128; off > 0; off >>= 1) {
        if (threadIdx.x < off) red[threadIdx.x] += red[threadIdx.x + off];
        __syncthreads();
    }
    if (threadIdx.x == 0)
        wsc[b] = fmaxf(red[0] * (1.0f/576.0f), 2e-16f);
}

// -------- sign extraction: stage0 as ±1 floats, stages 1-3 packed s8 --
__global__ void sign_kernel(const float* __restrict__ w,
                            float* __restrict__ w0, unsigned* __restrict__ sgn) {
    int t = blockIdx.x * 256 + threadIdx.x;
    if (t < 64*9*64) {            // stage0 floats [ci][tap][co]
        int co = t & 63;
        int tap = (t >> 6) % 9;
        int ci = t / 576;
        float v = w[((0*64 + co)*64 + ci)*9 + tap];
        w0[t] = (v >= 0.f) ? 1.f : -1.f;
    }
    if (t < 3*9216) {             // stages 1..3: [i-1][ci4][tap][co] packed
        int i   = t / 9216 + 1;
        int rem = t % 9216;
        int co  = rem & 63;
        int tap = (rem >> 6) % 9;
        int ci4 = rem / 576;
        unsigned word = 0;
        #pragma unroll
        for (int b = 0; b < 4; b++) {
            int ci = ci4*4 + b;
            float v = w[((i*64 + co)*64 + ci)*9 + tap];
            unsigned s = (v >= 0.f) ? 0x01u : 0xFFu;
            word |= s << (8*b);
        }
        sgn[t] = word;
    }
}

// -------- int8 narrow-range weight quant for 1x1, transposed [ci][co] -
__global__ void int8q_kernel(const float* __restrict__ w, float* __restrict__ dsq_t) {
    int co = blockIdx.x;
    const float* wc = w + co*64;
    __shared__ float red[64];
    int ci = threadIdx.x;
    red[ci] = fabsf(wc[ci]);
    __syncthreads();
    for (int off = 32; off > 0; off >>= 1) {
        if (ci < off) red[ci] = fmaxf(red[ci], red[ci + off]);
        __syncthreads();
    }
    float scale = fmaxf(red[0], 2e-16f) / 127.0f;
    float q = fminf(fmaxf(rintf(__fdiv_rn(wc[ci], scale)), -127.f), 127.f) * scale;
    dsq_t[ci*64 + co] = q;
}

// -------- fused BN / conv-scale coefficients --------------------------
__global__ void bncoef_kernel(const float* __restrict__ g, const float* __restrict__ b,
                              const float* __restrict__ m, const float* __restrict__ v,
                              const float* __restrict__ wsc,
                              float* __restrict__ A, float* __restrict__ B,
                              float* __restrict__ inv4, float* __restrict__ bias4) {
    int i = threadIdx.x;   // 320
    float iv = g[i] * __fdiv_rn(1.0f, __fsqrt_rn(v[i] + 1e-5f));
    float bias = b[i] - m[i] * iv;
    if (i < 256) {
        int s = i >> 6;
        float a = wsc[i] * iv;
        if (s > 0) a *= R_S;
        A[i] = a;
        B[i] = bias;
    } else {
        inv4[i - 256]  = iv;
        bias4[i - 256] = bias;
    }
}

// -------- 1x1 conv (downsample) + bn4 + qhtanh → packed s8 codes ------
__global__ __launch_bounds__(256, 2)
void conv1x1_kernel(const float* __restrict__ x, const float* __restrict__ wt,
                    const float* __restrict__ bninv, const float* __restrict__ bnbias,
                    unsigned* __restrict__ out) {
    int b  = blockIdx.x;          // 784 = 16 * 49
    int n  = b / 49;
    int p0 = (b - n*49) * 256;
    __shared__ float xs[16][256];
    __shared__ float ws[16][64];
    int t   = threadIdx.x;
    int pl  = t & 63;
    int cog = t >> 6;             // 0..3
    float acc[4][16];
    #pragma unroll
    for (int j = 0; j < 4; j++)
        #pragma unroll
        for (int k = 0; k < 16; k++) acc[j][k] = 0.f;

    const float* xN = x + n*CC*HWHW + p0;
    for (int c0 = 0; c0 < CC; c0 += 16) {
        __syncthreads();
        #pragma unroll
        for (int r = 0; r < 16; r++) xs[r][t] = xN[(c0 + r)*HWHW + t];
        #pragma unroll
        for (int r = 0; r < 4; r++) {
            int e = t + r*256;
            ws[e >> 6][e & 63] = wt[(c0 + (e >> 6))*64 + (e & 63)];
        }
        __syncthreads();
        #pragma unroll
        for (int ci = 0; ci < 16; ci++) {
            float wv[16];
            #pragma unroll
            for (int k = 0; k < 16; k++) wv[k] = ws[ci][cog*16 + k];
            #pragma unroll
            for (int j = 0; j < 4; j++) {
                float xv = xs[ci][pl + 64*j];
                #pragma unroll
                for (int k = 0; k < 16; k++) acc[j][k] = fmaf(xv, wv[k], acc[j][k]);
            }
        }
    }
    #pragma unroll
    for (int j = 0; j < 4; j++) {
        int pix = p0 + pl + 64*j;
        unsigned words[4] = {0,0,0,0};
        #pragma unroll
        for (int k = 0; k < 16; k++) {
            int co = cog*16 + k;
            float v = fmaf(acc[j][k], bninv[co], bnbias[co]);
            float c = fminf(fmaxf(v, -10.0f), 10.0f);
            float r = fminf(fmaxf(rintf(__fdiv_rn(c, HT_S)), -127.f), 127.f);
            unsigned byte = ((unsigned)(int)r) & 0xFFu;
            words[k >> 2] |= byte << (8*(k & 3));
        }
        #pragma unroll
        for (int q = 0; q < 4; q++)
            out[(n*16 + cog*4 + q)*HWHW + pix] = words[q];
    }
}

// -------- stage 0: fp32 3x3 conv (±1 weights) + EPI0 → packed u8 codes
__global__ __launch_bounds__(256, 2)
void conv3x3_fp0(const float* __restrict__ in, const float* __restrict__ wq,
                 const float* __restrict__ A, const float* __restrict__ B,
                 unsigned* __restrict__ out) {
    __shared__ float in_s[8][18][20];
    __shared__ __align__(16) float w_s[8*9*64];

    int t  = threadIdx.x;
    int n  = blockIdx.z;
    int h0 = blockIdx.y * TH;
    int w0 = blockIdx.x * TW;

    int pg  = t & 31;
    int cg  = t >> 5;
    int pw  = pg & 15;
    int phb = pg >> 4;

    const float* inN = in + n*CC*HWHW;

    float acc[8][8];
    #pragma unroll
    for (int j = 0; j < 8; j++)
        #pragma unroll
        for (int k = 0; k < 8; k++) acc[j][k] = 0.f;

    for (int c0 = 0; c0 < CC; c0 += 8) {
        __syncthreads();
        for (int e = t; e < 8*18*18; e += 256) {
            int ci  = e / 324;
            int pos = e - ci*324;
            int r   = pos / 18;
            int c   = pos - r*18;
            int hh = h0 - 1 + r;
            int ww = w0 - 1 + c;
            float v = 0.f;
            if ((unsigned)hh < HH && (unsigned)ww < WW)
                v = inN[(c0+ci)*HWHW + hh*WW + ww];
            in_s[ci][r][c] = v;
        }
        const float* wg = wq + c0*(9*CC);
        for (int e = t; e < 8*9*CC; e += 256) w_s[e] = wg[e];
        __syncthreads();

        #pragma unroll 1
        for (int ci = 0; ci < 8; ci++) {
            #pragma unroll
            for (int dy = 0; dy < 3; dy++) {
                #pragma unroll
                for (int dx = 0; dx < 3; dx++) {
                    float wv[8];
                    #pragma unroll
                    for (int k = 0; k < 8; k++)
                        wv[k] = w_s[(ci*9 + dy*3 + dx)*CC + cg*8 + k];
                    #pragma unroll
                    for (int j = 0; j < 8; j++) {
                        float iv = in_s[ci][phb + 2*j + dy][pw + dx];
                        #pragma unroll
                        for (int k = 0; k < 8; k++)
                            acc[j][k] = fmaf(iv, wv[k], acc[j][k]);
                    }
                }
            }
        }
    }

    float Av[8], Bv[8];
    #pragma unroll
    for (int k = 0; k < 8; k++) { Av[k] = A[cg*8+k]; Bv[k] = B[cg*8+k]; }
    int wcol = w0 + pw;
    #pragma unroll
    for (int j = 0; j < 8; j++) {
        int h = h0 + phb + 2*j;
        int pix = h*WW + wcol;
        unsigned outw0 = 0, outw1 = 0;
        #pragma unroll
        for (int k = 0; k < 8; k++) {
            int co = cg*8 + k;
            float v = fmaf(acc[j][k], Av[k], Bv[k]);
            float xv = in[(n*CC + co)*HWHW + pix];
            float r = qhtanh_f(v) + qhtanh_f(xv);
            unsigned code = qrelu_code(r);
            if (k < 4) outw0 |= code << (8*k);
            else       outw1 |= code << (8*(k-4));
        }
        int wbase = (n*16 + cg*2)*HWHW + pix;
        out[wbase]        = outw0;
        out[wbase + HWHW] = outw1;
    }
}

// -------- stages 1-3: exact u8×s8 dp4a conv + fused epilogue -----------
// EPI 0: r = qh(v)+qh(in)                       → u8 codes
// EPI 1: t = qh(v)+e1(s8*HT); r = qh(t)+qh(in)  → u8 codes
// EPI 3: t = qh(v)+qh(e1);    r = qh(in)+qh(t)  → fp32 final output
template<int EPI>
__global__ __launch_bounds__(256, 2)
void conv3x3_int(const unsigned* __restrict__ in, const unsigned* __restrict__ sgn,
                 const float* __restrict__ A, const float* __restrict__ B,
                 const unsigned* __restrict__ e1,
                 unsigned* __restrict__ outp, float* __restrict__ outf) {
    __shared__ unsigned in_s[4][18][24];         // pitch 24 → conflict-free
    __shared__ __align__(16) unsigned w_s[4*9*64];

    int t  = threadIdx.x;
    int n  = blockIdx.z;
    int h0 = blockIdx.y * TH;
    int w0 = blockIdx.x * TW;

    int pg  = t & 31;
    int cg  = t >> 5;
    int pw  = pg & 15;
    int phb = pg >> 4;

    const unsigned* inN = in + n*16*HWHW;

    int acc[8][8];
    #pragma unroll
    for (int j = 0; j < 8; j++)
        #pragma unroll
        for (int k = 0; k < 8; k++) acc[j][k] = 0;

    for (int c0 = 0; c0 < 16; c0 += 4) {          // 4 chunks of 4 packed-words (16 ch)
        __syncthreads();
        for (int e = t; e < 4*18*18; e += 256) {
            int l   = e / 324;
            int pos = e - l*324;
            int r   = pos / 18;
            int c   = pos - r*18;
            int hh = h0 - 1 + r;
            int ww = w0 - 1 + c;
            unsigned v = 0;
            if ((unsigned)hh < HH && (unsigned)ww < WW)
                v = inN[(c0+l)*HWHW + hh*WW + ww];
            in_s[l][r][c] = v;
        }
        const unsigned* wg = sgn + c0*576;        // contiguous slab [4][9][64]
        for (int e = t; e < 4*9*64; e += 256) w_s[e] = wg[e];
        __syncthreads();

        #pragma unroll 1
        for (int l = 0; l < 4; l++) {
            #pragma unroll
            for (int dy = 0; dy < 3; dy++) {
                #pragma unroll
                for (int dx = 0; dx < 3; dx++) {
                    uint4 wa = *(const uint4*)&w_s[(l*9 + dy*3 + dx)*64 + cg*8];
                    uint4 wb = *(const uint4*)&w_s[(l*9 + dy*3 + dx)*64 + cg*8 + 4];
                    #pragma unroll
                    for (int j = 0; j < 8; j++) {
                        unsigned iv = in_s[l][phb + 2*j + dy][pw + dx];
                        acc[j][0] = dp4a_us(iv, wa.x, acc[j][0]);
                        acc[j][1] = dp4a_us(iv, wa.y, acc[j][1]);
                        acc[j][2] = dp4a_us(iv, wa.z, acc[j][2]);
                        acc[j][3] = dp4a_us(iv, wa.w, acc[j][3]);
                        acc[j][4] = dp4a_us(iv, wb.x, acc[j][4]);
                        acc[j][5] = dp4a_us(iv, wb.y, acc[j][5]);
                        acc[j][6] = dp4a_us(iv, wb.z, acc[j][6]);
                        acc[j][7] = dp4a_us(iv, wb.w, acc[j][7]);
                    }
                }
            }
        }
    }

    float Av[8], Bv[8];
    #pragma unroll
    for (int k = 0; k < 8; k++) { Av[k] = A[cg*8+k]; Bv[k] = B[cg*8+k]; }
    int wcol = w0 + pw;
    #pragma unroll
    for (int j = 0; j < 8; j++) {
        int h   = h0 + phb + 2*j;
        int pix = h*WW + wcol;
        int wbase = (n*16 + cg*2)*HWHW + pix;
        unsigned inw0 = in[wbase], inw1 = in[wbase + HWHW];
        unsigned e1w0 = 0, e1w1 = 0;
        if (EPI == 1 || EPI == 3) { e1w0 = e1[wbase]; e1w1 = e1[wbase + HWHW]; }
        unsigned outw0 = 0, outw1 = 0;
        #pragma unroll
        for (int k = 0; k < 8; k++) {
            float v = fmaf((float)acc[j][k], Av[k], Bv[k]);
            unsigned inw = (k < 4) ? inw0 : inw1;
            float in_val = (float)((inw >> (8*(k & 3))) & 255u) * R_S;
            float r;
            if (EPI == 0) {
                r = qhtanh_f(v) + qhtanh_f(in_val);
            } else if (EPI == 1) {
                unsigned ew = (k < 4) ? e1w0 : e1w1;
                int ec = (int)(ew << (24 - 8*(k & 3))) >> 24;   // s8 extract
                float tq = qhtanh_f(v) + (float)ec * HT_S;
                r = qhtanh_f(tq) + qhtanh_f(in_val);
            } else {  // EPI == 3
                unsigned ew = (k < 4) ? e1w0 : e1w1;
                float e_val = (float)((ew >> (8*(k & 3))) & 255u) * R_S;
                float tq = qhtanh_f(v) + qhtanh_f(e_val);
                r = qhtanh_f(in_val) + qhtanh_f(tq);
            }
            if (EPI == 3) {
                outf[(n*CC + cg*8 + k)*HWHW + pix] = qrelu_f(r);
            } else {
                unsigned code = qrelu_code(r);
                if (k < 4) outw0 |= code << (8*k);
                else       outw1 |= code << (8*(k-4));
            }
        }
        if (EPI != 3) {
            outp[wbase]        = outw0;
            outp[wbase + HWHW] = outw1;
        }
    }
}

// -------------------- host launcher --------------------------------
extern "C" void kernel_launch(void* const* d_in, const int* in_sizes, int n_in,
                              void* d_out, int out_size) {
    const float* x      = (const float*)d_in[0];
    const float* conv_w = (const float*)d_in[1];
    const float* ds_w   = (const float*)d_in[2];
    const float* bng    = (const float*)d_in[3];
    const float* bnb    = (const float*)d_in[4];
    const float* bnm    = (const float*)d_in[5];
    const float* bnvv   = (const float*)d_in[6];
    float* out = (float*)d_out;

    unsigned *act1, *act2, *act3, *idq, *sgn;
    float *w0, *dsq, *wsc, *A, *B, *inv4, *bias4;
    cudaGetSymbolAddress((void**)&act1, g_act1);
    cudaGetSymbolAddress((void**)&act2, g_act2);
    cudaGetSymbolAddress((void**)&act3, g_act3);
    cudaGetSymbolAddress((void**)&idq,  g_idq);
    cudaGetSymbolAddress((void**)&sgn,  g_sgn);
    cudaGetSymbolAddress((void**)&w0,   g_w0);
    cudaGetSymbolAddress((void**)&dsq,  g_dsq);
    cudaGetSymbolAddress((void**)&wsc,  g_wsc);
    cudaGetSymbolAddress((void**)&A,    g_A);
    cudaGetSymbolAddress((void**)&B,    g_B);
    cudaGetSymbolAddress((void**)&inv4, g_bninv4);
    cudaGetSymbolAddress((void**)&bias4,g_bnbias4);

    // weight prep
    scale_kernel<<<256, 256>>>(conv_w, wsc);
    sign_kernel<<<144, 256>>>(conv_w, w0, sgn);
    int8q_kernel<<<64, 64>>>(ds_w, dsq);
    bncoef_kernel<<<1, 320>>>(bng, bnb, bnm, bnvv, wsc, A, B, inv4, bias4);

    // downsample identity path → packed s8 codes
    conv1x1_kernel<<<784, 256>>>(x, dsq, inv4, bias4, idq);

    dim3 grid(WW/TW, HH/TH, NN);   // (7,7,16)
    // stage 0: fp32 conv on x → act1 (u8 codes)
    conv3x3_fp0<<<grid, 256>>>(x, w0, A + 0*CC, B + 0*CC, act1);
    // stage 1: int conv, uses identity0 (s8 codes)
    conv3x3_int<1><<<grid, 256>>>(act1, sgn + 0*9216, A + 1*CC, B + 1*CC, idq,  act2, nullptr);
    // stage 2: int conv
    conv3x3_int<0><<<grid, 256>>>(act2, sgn + 1*9216, A + 2*CC, B + 2*CC, nullptr, act3, nullptr);
    // stage 3: int conv, uses s2, writes fp32 final output
    conv3x3_int<3><<<grid, 256>>>(act3, sgn + 2*9216, A + 3*CC, B + 3*CC, act2, nullptr, out);
}

// round 5
// speedup vs baseline: 1.0161x; 1.0161x over previous
#include <cuda_runtime.h>
#include <cuda_bf16.h>

// Problem constants
#define NN 16
#define CC 64
#define HH 112
#define WW 112
#define HWHW (HH*WW)               // 12544
#define TENSOR_ELEMS (NN*CC*HWHW)  // 12,845,056
#define PKW (NN*16*HWHW)           // packed words (4 channels / u32)

#define TH 16
#define TW 16

#define R_S  (10.0f/255.0f)
#define HT_S (10.0f/127.0f)

// -------- scratch (device globals; no allocation allowed) ----------
__device__ unsigned g_act1[PKW];          // u8 codes, [n][c4][h][w]
__device__ unsigned g_act2[PKW];
__device__ unsigned g_act3[PKW];
__device__ unsigned g_idq [PKW];          // s8 codes of qhtanh(identity0)
__device__ unsigned g_sgn [3*16*9*64];    // stages 1..3: packed ±1 s8, [i-1][ci4][tap][co]
__device__ float    g_w0  [64*9*64];      // stage0 ±1 floats, [ci][tap][co]
__device__ float    g_dsq [CC*CC];        // int8-quant 1x1 weights, [ci][co]
__device__ float    g_wsc [4*CC];         // binary weight per-channel scales
__device__ float    g_A   [4*CC];         // fused conv-scale * bn-inv (stage>0 includes R)
__device__ float    g_B   [4*CC];         // bn bias
__device__ float    g_bninv4 [CC];
__device__ float    g_bnbias4[CC];

// -------- f32x2 packed helpers (Blackwell FFMA2 path) ---------------
__device__ __forceinline__ unsigned long long pack_dup(float v) {
    unsigned long long r;
    asm("mov.b64 %0, {%1, %1};" : "=l"(r) : "f"(v));
    return r;
}
__device__ __forceinline__ unsigned long long fma2(unsigned long long a,
                                                   unsigned long long b,
                                                   unsigned long long c) {
    unsigned long long d;
    asm("fma.rn.f32x2 %0, %1, %2, %3;" : "=l"(d) : "l"(a), "l"(b), "l"(c));
    return d;
}
__device__ __forceinline__ void unpack2(unsigned long long v, float& lo, float& hi) {
    asm("mov.b64 {%0, %1}, %2;" : "=f"(lo), "=f"(hi) : "l"(v));
}

// -------- quantizer helpers (round-half-even matches jnp) -----------
__device__ __forceinline__ float qhtanh_f(float x) {
    float c = fminf(fmaxf(x, -10.0f), 10.0f);
    float r = rintf(__fdiv_rn(c, HT_S));
    r = fminf(fmaxf(r, -127.0f), 127.0f);
    return r * HT_S;
}
__device__ __forceinline__ float qrelu_f(float x) {
    float c = fminf(fmaxf(x, 0.0f), 10.0f);
    float r = rintf(__fdiv_rn(c, R_S));
    r = fminf(fmaxf(r, 0.0f), 255.0f);
    return r * R_S;
}
__device__ __forceinline__ unsigned qrelu_code(float x) {
    float c = fminf(fmaxf(x, 0.0f), 10.0f);
    float r = rintf(__fdiv_rn(c, R_S));
    return (unsigned)(int)fminf(r, 255.0f);
}
__device__ __forceinline__ int dp4a_us(unsigned a, unsigned b, int c) {
    int r;
    asm("dp4a.u32.s32 %0, %1, %2, %3;" : "=r"(r) : "r"(a), "r"(b), "r"(c));
    return r;
}

// -------- per-channel AVE scale for binary weights -------------------
__global__ void scale_kernel(const float* __restrict__ w, float* __restrict__ wsc) {
    int b  = blockIdx.x;          // 0..255
    const float* wc = w + b*576;
    __shared__ float red[256];
    float s = 0.f;
    for (int e = threadIdx.x; e < 576; e += 256) s += fabsf(wc[e]);
    red[threadIdx.x] = s;
    __syncthreads();
    for (int off = 128; off > 0; off >>= 1) {
        if (threadIdx.x < off) red[threadIdx.x] += red[threadIdx.x + off];
        __syncthreads();
    }
    if (threadIdx.x == 0)
        wsc[b] = fmaxf(red[0] * (1.0f/576.0f), 2e-16f);
}

// -------- sign extraction: stage0 as ±1 floats, stages 1-3 packed s8 --
__global__ void sign_kernel(const float* __restrict__ w,
                            float* __restrict__ w0, unsigned* __restrict__ sgn) {
    int t = blockIdx.x * 256 + threadIdx.x;
    if (t < 64*9*64) {            // stage0 floats [ci][tap][co]
        int co = t & 63;
        int tap = (t >> 6) % 9;
        int ci = t / 576;
        float v = w[((0*64 + co)*64 + ci)*9 + tap];
        w0[t] = (v >= 0.f) ? 1.f : -1.f;
    }
    if (t < 3*9216) {             // stages 1..3: [i-1][ci4][tap][co] packed
        int i   = t / 9216 + 1;
        int rem = t % 9216;
        int co  = rem & 63;
        int tap = (rem >> 6) % 9;
        int ci4 = rem / 576;
        unsigned word = 0;
        #pragma unroll
        for (int b = 0; b < 4; b++) {
            int ci = ci4*4 + b;
            float v = w[((i*64 + co)*64 + ci)*9 + tap];
            unsigned s = (v >= 0.f) ? 0x01u : 0xFFu;
            word |= s << (8*b);
        }
        sgn[t] = word;
    }
}

// -------- int8 narrow-range weight quant for 1x1, transposed [ci][co] -
__global__ void int8q_kernel(const float* __restrict__ w, float* __restrict__ dsq_t) {
    int co = blockIdx.x;
    const float* wc = w + co*64;
    __shared__ float red[64];
    int ci = threadIdx.x;
    red[ci] = fabsf(wc[ci]);
    __syncthreads();
    for (int off = 32; off > 0; off >>= 1) {
        if (ci < off) red[ci] = fmaxf(red[ci], red[ci + off]);
        __syncthreads();
    }
    float scale = fmaxf(red[0], 2e-16f) / 127.0f;
    float q = fminf(fmaxf(rintf(__fdiv_rn(wc[ci], scale)), -127.f), 127.f) * scale;
    dsq_t[ci*64 + co] = q;
}

// -------- fused BN / conv-scale coefficients --------------------------
__global__ void bncoef_kernel(const float* __restrict__ g, const float* __restrict__ b,
                              const float* __restrict__ m, const float* __restrict__ v,
                              const float* __restrict__ wsc,
                              float* __restrict__ A, float* __restrict__ B,
                              float* __restrict__ inv4, float* __restrict__ bias4) {
    int i = threadIdx.x;   // 320
    float iv = g[i] * __fdiv_rn(1.0f, __fsqrt_rn(v[i] + 1e-5f));
    float bias = b[i] - m[i] * iv;
    if (i < 256) {
        int s = i >> 6;
        float a = wsc[i] * iv;
        if (s > 0) a *= R_S;
        A[i] = a;
        B[i] = bias;
    } else {
        inv4[i - 256]  = iv;
        bias4[i - 256] = bias;
    }
}

// -------- 1x1 conv (downsample) + bn4 + qhtanh → packed s8 codes ------
__global__ __launch_bounds__(256, 2)
void conv1x1_kernel(const float* __restrict__ x, const float* __restrict__ wt,
                    const float* __restrict__ bninv, const float* __restrict__ bnbias,
                    unsigned* __restrict__ out) {
    int b  = blockIdx.x;          // 784 = 16 * 49
    int n  = b / 49;
    int p0 = (b - n*49) * 256;
    __shared__ float xs[16][256];
    __shared__ __align__(8) float ws[16][64];
    int t   = threadIdx.x;
    int pl  = t & 63;
    int cog = t >> 6;             // 0..3
    unsigned long long acc2[4][8];
    #pragma unroll
    for (int j = 0; j < 4; j++)
        #pragma unroll
        for (int k2 = 0; k2 < 8; k2++) acc2[j][k2] = 0ULL;

    const float* xN = x + n*CC*HWHW + p0;
    for (int c0 = 0; c0 < CC; c0 += 16) {
        __syncthreads();
        #pragma unroll
        for (int r = 0; r < 16; r++) xs[r][t] = xN[(c0 + r)*HWHW + t];
        #pragma unroll
        for (int r = 0; r < 4; r++) {
            int e = t + r*256;
            ws[e >> 6][e & 63] = wt[(c0 + (e >> 6))*64 + (e & 63)];
        }
        __syncthreads();
        #pragma unroll
        for (int ci = 0; ci < 16; ci++) {
            unsigned long long w2[8];
            #pragma unroll
            for (int k2 = 0; k2 < 8; k2++)
                w2[k2] = *(const unsigned long long*)&ws[ci][cog*16 + 2*k2];
            #pragma unroll
            for (int j = 0; j < 4; j++) {
                unsigned long long xv2 = pack_dup(xs[ci][pl + 64*j]);
                #pragma unroll
                for (int k2 = 0; k2 < 8; k2++)
                    acc2[j][k2] = fma2(xv2, w2[k2], acc2[j][k2]);
            }
        }
    }
    #pragma unroll
    for (int j = 0; j < 4; j++) {
        int pix = p0 + pl + 64*j;
        unsigned words[4] = {0,0,0,0};
        #pragma unroll
        for (int k2 = 0; k2 < 8; k2++) {
            float a0, a1;
            unpack2(acc2[j][k2], a0, a1);
            #pragma unroll
            for (int h = 0; h < 2; h++) {
                int k  = 2*k2 + h;
                int co = cog*16 + k;
                float v = fmaf(h ? a1 : a0, bninv[co], bnbias[co]);
                float c = fminf(fmaxf(v, -10.0f), 10.0f);
                float r = fminf(fmaxf(rintf(__fdiv_rn(c, HT_S)), -127.f), 127.f);
                unsigned byte = ((unsigned)(int)r) & 0xFFu;
                words[k >> 2] |= byte << (8*(k & 3));
            }
        }
        #pragma unroll
        for (int q = 0; q < 4; q++)
            out[(n*16 + cog*4 + q)*HWHW + pix] = words[q];
    }
}

// -------- stage 0: fp32 3x3 conv (±1 weights, FFMA2) + EPI0 → u8 codes
__global__ __launch_bounds__(256, 2)
void conv3x3_fp0(const float* __restrict__ in, const float* __restrict__ wq,
                 const float* __restrict__ A, const float* __restrict__ B,
                 unsigned* __restrict__ out) {
    __shared__ float in_s[8][18][20];
    __shared__ __align__(16) float w_s[8*9*64];

    int t  = threadIdx.x;
    int n  = blockIdx.z;
    int h0 = blockIdx.y * TH;
    int w0 = blockIdx.x * TW;

    int pg  = t & 31;
    int cg  = t >> 5;
    int pw  = pg & 15;
    int phb = pg >> 4;

    const float* inN = in + n*CC*HWHW;

    unsigned long long acc2[8][4];
    #pragma unroll
    for (int j = 0; j < 8; j++)
        #pragma unroll
        for (int k2 = 0; k2 < 4; k2++) acc2[j][k2] = 0ULL;

    for (int c0 = 0; c0 < CC; c0 += 8) {
        __syncthreads();
        for (int e = t; e < 8*18*18; e += 256) {
            int ci  = e / 324;
            int pos = e - ci*324;
            int r   = pos / 18;
            int c   = pos - r*18;
            int hh = h0 - 1 + r;
            int ww = w0 - 1 + c;
            float v = 0.f;
            if ((unsigned)hh < HH && (unsigned)ww < WW)
                v = inN[(c0+ci)*HWHW + hh*WW + ww];
            in_s[ci][r][c] = v;
        }
        const float* wg = wq + c0*(9*CC);
        for (int e = t; e < 8*9*CC; e += 256) w_s[e] = wg[e];
        __syncthreads();

        #pragma unroll 1
        for (int ci = 0; ci < 8; ci++) {
            #pragma unroll
            for (int dy = 0; dy < 3; dy++) {
                #pragma unroll
                for (int dx = 0; dx < 3; dx++) {
                    unsigned long long w2[4];
                    #pragma unroll
                    for (int k2 = 0; k2 < 4; k2++)
                        w2[k2] = *(const unsigned long long*)
                                 &w_s[(ci*9 + dy*3 + dx)*CC + cg*8 + 2*k2];
                    #pragma unroll
                    for (int j = 0; j < 8; j++) {
                        unsigned long long iv2 =
                            pack_dup(in_s[ci][phb + 2*j + dy][pw + dx]);
                        #pragma unroll
                        for (int k2 = 0; k2 < 4; k2++)
                            acc2[j][k2] = fma2(iv2, w2[k2], acc2[j][k2]);
                    }
                }
            }
        }
    }

    float Av[8], Bv[8];
    #pragma unroll
    for (int k = 0; k < 8; k++) { Av[k] = A[cg*8+k]; Bv[k] = B[cg*8+k]; }
    int wcol = w0 + pw;
    #pragma unroll
    for (int j = 0; j < 8; j++) {
        int h = h0 + phb + 2*j;
        int pix = h*WW + wcol;
        unsigned outw0 = 0, outw1 = 0;
        float accf[8];
        #pragma unroll
        for (int k2 = 0; k2 < 4; k2++)
            unpack2(acc2[j][k2], accf[2*k2], accf[2*k2+1]);
        #pragma unroll
        for (int k = 0; k < 8; k++) {
            int co = cg*8 + k;
            float v = fmaf(accf[k], Av[k], Bv[k]);
            float xv = in[(n*CC + co)*HWHW + pix];
            float r = qhtanh_f(v) + qhtanh_f(xv);
            unsigned code = qrelu_code(r);
            if (k < 4) outw0 |= code << (8*k);
            else       outw1 |= code << (8*(k-4));
        }
        int wbase = (n*16 + cg*2)*HWHW + pix;
        out[wbase]        = outw0;
        out[wbase + HWHW] = outw1;
    }
}

// -------- stages 1-3: exact u8×s8 dp4a conv + fused epilogue -----------
template<int EPI>
__global__ __launch_bounds__(256, 2)
void conv3x3_int(const unsigned* __restrict__ in, const unsigned* __restrict__ sgn,
                 const float* __restrict__ A, const float* __restrict__ B,
                 const unsigned* __restrict__ e1,
                 unsigned* __restrict__ outp, float* __restrict__ outf) {
    __shared__ unsigned in_s[4][18][24];         // pitch 24 → conflict-free
    __shared__ __align__(16) unsigned w_s[4*9*64];

    int t  = threadIdx.x;
    int n  = blockIdx.z;
    int h0 = blockIdx.y * TH;
    int w0 = blockIdx.x * TW;

    int pg  = t & 31;
    int cg  = t >> 5;
    int pw  = pg & 15;
    int phb = pg >> 4;

    const unsigned* inN = in + n*16*HWHW;

    int acc[8][8];
    #pragma unroll
    for (int j = 0; j < 8; j++)
        #pragma unroll
        for (int k = 0; k < 8; k++) acc[j][k] = 0;

    for (int c0 = 0; c0 < 16; c0 += 4) {
        __syncthreads();
        for (int e = t; e < 4*18*18; e += 256) {
            int l   = e / 324;
            int pos = e - l*324;
            int r   = pos / 18;
            int c   = pos - r*18;
            int hh = h0 - 1 + r;
            int ww = w0 - 1 + c;
            unsigned v = 0;
            if ((unsigned)hh < HH && (unsigned)ww < WW)
                v = inN[(c0+l)*HWHW + hh*WW + ww];
            in_s[l][r][c] = v;
        }
        const unsigned* wg = sgn + c0*576;
        for (int e = t; e < 4*9*64; e += 256) w_s[e] = wg[e];
        __syncthreads();

        #pragma unroll 1
        for (int l = 0; l < 4; l++) {
            #pragma unroll
            for (int dy = 0; dy < 3; dy++) {
                #pragma unroll
                for (int dx = 0; dx < 3; dx++) {
                    uint4 wa = *(const uint4*)&w_s[(l*9 + dy*3 + dx)*64 + cg*8];
                    uint4 wb = *(const uint4*)&w_s[(l*9 + dy*3 + dx)*64 + cg*8 + 4];
                    #pragma unroll
                    for (int j = 0; j < 8; j++) {
                        unsigned iv = in_s[l][phb + 2*j + dy][pw + dx];
                        acc[j][0] = dp4a_us(iv, wa.x, acc[j][0]);
                        acc[j][1] = dp4a_us(iv, wa.y, acc[j][1]);
                        acc[j][2] = dp4a_us(iv, wa.z, acc[j][2]);
                        acc[j][3] = dp4a_us(iv, wa.w, acc[j][3]);
                        acc[j][4] = dp4a_us(iv, wb.x, acc[j][4]);
                        acc[j][5] = dp4a_us(iv, wb.y, acc[j][5]);
                        acc[j][6] = dp4a_us(iv, wb.z, acc[j][6]);
                        acc[j][7] = dp4a_us(iv, wb.w, acc[j][7]);
                    }
                }
            }
        }
    }

    float Av[8], Bv[8];
    #pragma unroll
    for (int k = 0; k < 8; k++) { Av[k] = A[cg*8+k]; Bv[k] = B[cg*8+k]; }
    int wcol = w0 + pw;
    #pragma unroll
    for (int j = 0; j < 8; j++) {
        int h   = h0 + phb + 2*j;
        int pix = h*WW + wcol;
        int wbase = (n*16 + cg*2)*HWHW + pix;
        unsigned inw0 = in[wbase], inw1 = in[wbase + HWHW];
        unsigned e1w0 = 0, e1w1 = 0;
        if (EPI == 1 || EPI == 3) { e1w0 = e1[wbase]; e1w1 = e1[wbase + HWHW]; }
        unsigned outw0 = 0, outw1 = 0;
        #pragma unroll
        for (int k = 0; k < 8; k++) {
            float v = fmaf((float)acc[j][k], Av[k], Bv[k]);
            unsigned inw = (k < 4) ? inw0 : inw1;
            float in_val = (float)((inw >> (8*(k & 3))) & 255u) * R_S;
            float r;
            if (EPI == 0) {
                r = qhtanh_f(v) + qhtanh_f(in_val);
            } else if (EPI == 1) {
                unsigned ew = (k < 4) ? e1w0 : e1w1;
                int ec = (int)(ew << (24 - 8*(k & 3))) >> 24;   // s8 extract
                float tq = qhtanh_f(v) + (float)ec * HT_S;
                r = qhtanh_f(tq) + qhtanh_f(in_val);
            } else {  // EPI == 3
                unsigned ew = (k < 4) ? e1w0 : e1w1;
                float e_val = (float)((ew >> (8*(k & 3))) & 255u) * R_S;
                float tq = qhtanh_f(v) + qhtanh_f(e_val);
                r = qhtanh_f(in_val) + qhtanh_f(tq);
            }
            if (EPI == 3) {
                outf[(n*CC + cg*8 + k)*HWHW + pix] = qrelu_f(r);
            } else {
                unsigned code = qrelu_code(r);
                if (k < 4) outw0 |= code << (8*k);
                else       outw1 |= code << (8*(k-4));
            }
        }
        if (EPI != 3) {
            outp[wbase]        = outw0;
            outp[wbase + HWHW] = outw1;
        }
    }
}

// -------------------- host launcher --------------------------------
extern "C" void kernel_launch(void* const* d_in, const int* in_sizes, int n_in,
                              void* d_out, int out_size) {
    const float* x      = (const float*)d_in[0];
    const float* conv_w = (const float*)d_in[1];
    const float* ds_w   = (const float*)d_in[2];
    const float* bng    = (const float*)d_in[3];
    const float* bnb    = (const float*)d_in[4];
    const float* bnm    = (const float*)d_in[5];
    const float* bnvv   = (const float*)d_in[6];
    float* out = (float*)d_out;

    unsigned *act1, *act2, *act3, *idq, *sgn;
    float *w0, *dsq, *wsc, *A, *B, *inv4, *bias4;
    cudaGetSymbolAddress((void**)&act1, g_act1);
    cudaGetSymbolAddress((void**)&act2, g_act2);
    cudaGetSymbolAddress((void**)&act3, g_act3);
    cudaGetSymbolAddress((void**)&idq,  g_idq);
    cudaGetSymbolAddress((void**)&sgn,  g_sgn);
    cudaGetSymbolAddress((void**)&w0,   g_w0);
    cudaGetSymbolAddress((void**)&dsq,  g_dsq);
    cudaGetSymbolAddress((void**)&wsc,  g_wsc);
    cudaGetSymbolAddress((void**)&A,    g_A);
    cudaGetSymbolAddress((void**)&B,    g_B);
    cudaGetSymbolAddress((void**)&inv4, g_bninv4);
    cudaGetSymbolAddress((void**)&bias4,g_bnbias4);

    // weight prep
    scale_kernel<<<256, 256>>>(conv_w, wsc);
    sign_kernel<<<144, 256>>>(conv_w, w0, sgn);
    int8q_kernel<<<64, 64>>>(ds_w, dsq);
    bncoef_kernel<<<1, 320>>>(bng, bnb, bnm, bnvv, wsc, A, B, inv4, bias4);

    // downsample identity path → packed s8 codes
    conv1x1_kernel<<<784, 256>>>(x, dsq, inv4, bias4, idq);

    dim3 grid(WW/TW, HH/TH, NN);   // (7,7,16)
    // stage 0: fp32 FFMA2 conv on x → act1 (u8 codes)
    conv3x3_fp0<<<grid, 256>>>(x, w0, A + 0*CC, B + 0*CC, act1);
    // stage 1: int conv, uses identity0 (s8 codes)
    conv3x3_int<1><<<grid, 256>>>(act1, sgn + 0*9216, A + 1*CC, B + 1*CC, idq,  act2, nullptr);
    // stage 2: int conv
    conv3x3_int<0><<<grid, 256>>>(act2, sgn + 1*9216, A + 2*CC, B + 2*CC, nullptr, act3, nullptr);
    // stage 3: int conv, uses s2, writes fp32 final output
    conv3x3_int<3><<<grid, 256>>>(act3, sgn + 2*9216, A + 3*CC, B + 3*CC, act2, nullptr, out);
}